// round 3
// baseline (speedup 1.0000x reference)
#include <cuda_runtime.h>
#include <cstdint>
#include <cstddef>

#define NVEC 1024
#define NDIM 64
#define NHID 32
#define NW   10
#define NB   16
#define NOFF 11

// Scratch (no allocations allowed): device globals.
__device__ float g_w[NW * NB * NOFF * NVEC];   // per-layer sparse W values [i][b][o][n]
__device__ float g_V[NB * NVEC * NDIM];        // final V
__device__ float g_part[NB * 8 * 10];          // partial sums for output GEMM
__device__ int   g_cnt;                        // block completion counter (resets itself)

// ---------- f32x2 packed helpers (sm_103a FFMA2) ----------
__device__ __forceinline__ unsigned long long pack2(float x, float y) {
    unsigned long long r;
    asm("mov.b64 %0, {%1, %2};" : "=l"(r) : "f"(x), "f"(y));
    return r;
}
__device__ __forceinline__ void fma2(unsigned long long& d, unsigned long long a, unsigned long long b) {
    asm("fma.rn.f32x2 %0, %1, %2, %0;" : "+l"(d) : "l"(a), "l"(b));
}
__device__ __forceinline__ float2 unpack2(unsigned long long v) {
    float lo, hi;
    asm("mov.b64 {%0, %1}, %2;" : "=f"(lo), "=f"(hi) : "l"(v));
    return make_float2(lo, hi);
}
__device__ __forceinline__ float gelu_exact(float x) {
    return 0.5f * x * (1.0f + erff(x * 0.70710678f));
}

// ---------------------------------------------------------------------------
// Kernel 1: precompute sparse W values, register-tiled.
// Block: 256 threads, n-tile 256, 2 batches, 1 layer. Grid (4, 8, 10) = 320.
// Thread tile in the h-GEMM: 4n x 8h -> 0.25 smem reads per MAC.
// smem paddings chosen for conflict-free (or 2-way max) access everywhere.
// ---------------------------------------------------------------------------
#define SW2_COLS   768
#define SW2_STRIDE 34                     // even (ULL-aligned), 2-way worst case
#define XS         65                     // odd pad: conflict-free broadcast reads
#define HTS        33                     // odd pad: conflict-free row reads
// floats: sw2t 26112 + sw1 2048 + sfb1 32 + sfb2 768 + X 16640 + Ht 8448 = 54048
#define PRE_SMEM   (54048 * 4)

__global__ void __launch_bounds__(256) precompute_kernel(
    const float* __restrict__ data, const float* __restrict__ fW1,
    const float* __restrict__ fb1,  const float* __restrict__ fW2,
    const float* __restrict__ fb2)
{
    extern __shared__ float sm[];
    float* sw2t = sm;                         // [768][34] transposed fW2 tile
    float* sw1  = sw2t + SW2_COLS * SW2_STRIDE; // [64][32]
    float* sfb1 = sw1 + NDIM * NHID;          // [32]
    float* sfb2 = sfb1 + NHID;                // [768]
    float* Xs   = sfb2 + SW2_COLS;            // [256][65] data rows (padded)
    float* Hts  = Xs + 256 * XS;              // [256][33] gelu(h) rows (padded)

    const int t  = threadIdx.x;
    const int n0 = blockIdx.x * 256;
    const int bg = blockIdx.y;
    const int i  = blockIdx.z;

    // ---- Stage per-layer weights once (reused by both batches) ----
    for (int idx = t; idx < NDIM * NHID; idx += 256)
        sw1[idx] = fW1[i * NDIM * NHID + idx];
    if (t < NHID) sfb1[t] = fb1[i * NHID + t];
    for (int c = t; c < SW2_COLS; c += 256)
        sfb2[c] = fb2[i * NVEC + ((n0 + c) & (NVEC - 1))];
    for (int idx = t; idx < NHID * SW2_COLS; idx += 256) {
        int hh = idx / SW2_COLS;
        int c  = idx - hh * SW2_COLS;
        sw2t[c * SW2_STRIDE + hh] =
            fW2[((size_t)i * NHID + hh) * NVEC + ((n0 + c) & (NVEC - 1))];
    }

    const int ht8 = (t & 3) * 8;     // 8-wide h slice
    const int nb  = (t >> 2) * 4;    // 4-row n slice
    const int OFF[NOFF] = {0, 1, 2, 4, 8, 16, 32, 64, 128, 256, 512};

#pragma unroll 1
    for (int bb = 0; bb < 2; bb++) {
        const int b = bg * 2 + bb;

        // ---- Stage X tile (coalesced LDG.128, scalar STS, 2-way max) ----
        const float4* src =
            reinterpret_cast<const float4*>(data + ((size_t)b * NVEC + n0) * NDIM);
#pragma unroll
        for (int j = 0; j < 16; j++) {
            int p  = t + 256 * j;        // 4096 float4 total
            int n  = p >> 4;
            int kq = p & 15;
            float4 v = __ldg(src + p);
            float* dst = Xs + n * XS + kq * 4;
            dst[0] = v.x; dst[1] = v.y; dst[2] = v.z; dst[3] = v.w;
        }
        __syncthreads();   // X + (first iter) weights visible

        // ---- h-GEMM: 4n x 8h register tile, k = 0..63 ----
        unsigned long long acc[4][4];
        {
            const unsigned long long* bp =
                reinterpret_cast<const unsigned long long*>(&sfb1[ht8]);
            unsigned long long b0 = bp[0], b1 = bp[1], b2 = bp[2], b3 = bp[3];
#pragma unroll
            for (int j = 0; j < 4; j++) {
                acc[j][0] = b0; acc[j][1] = b1; acc[j][2] = b2; acc[j][3] = b3;
            }
        }
#pragma unroll 8
        for (int k = 0; k < NDIM; k++) {
            const unsigned long long* wp =
                reinterpret_cast<const unsigned long long*>(&sw1[k * NHID + ht8]);
            unsigned long long w0 = wp[0], w1 = wp[1], w2 = wp[2], w3 = wp[3];
#pragma unroll
            for (int j = 0; j < 4; j++) {
                float xv = Xs[(nb + j) * XS + k];      // broadcast, conflict-free
                unsigned long long xx = pack2(xv, xv);
                fma2(acc[j][0], xx, w0);
                fma2(acc[j][1], xx, w1);
                fma2(acc[j][2], xx, w2);
                fma2(acc[j][3], xx, w3);
            }
        }

        // ---- gelu + write H rows to smem ----
#pragma unroll
        for (int j = 0; j < 4; j++) {
#pragma unroll
            for (int p = 0; p < 4; p++) {
                float2 v = unpack2(acc[j][p]);
                Hts[(nb + j) * HTS + ht8 + 2 * p]     = gelu_exact(v.x);
                Hts[(nb + j) * HTS + ht8 + 2 * p + 1] = gelu_exact(v.y);
            }
        }
        __syncthreads();   // H complete

        // ---- sparse W2 stage: thread owns row n = t ----
        unsigned long long hr[16];
#pragma unroll
        for (int q = 0; q < 16; q++)
            hr[q] = pack2(Hts[t * HTS + 2 * q], Hts[t * HTS + 2 * q + 1]);

        float* out = g_w + (size_t)((i * NB + b) * NOFF) * NVEC + n0 + t;
#pragma unroll
        for (int o = 0; o < NOFF; o++) {
            int c = t + OFF[o];
            const unsigned long long* w2p =
                reinterpret_cast<const unsigned long long*>(&sw2t[c * SW2_STRIDE]);
            unsigned long long a2 = pack2(0.f, 0.f);
#pragma unroll
            for (int q = 0; q < 16; q++) fma2(a2, hr[q], w2p[q]);
            float2 s = unpack2(a2);
            out[(size_t)o * NVEC] = s.x + s.y + sfb2[c];
        }
        __syncthreads();   // all W2 reads done before next batch overwrites X/Ht
    }
}

// ---------------------------------------------------------------------------
// Kernel 2: the full 10-layer sparse recursion, V slice resident in smem.
// Ping-pong buffers (1 barrier/layer), residual + offset-0 term from registers,
// next layer's w prefetched so LDG latency hides under compute.
// ---------------------------------------------------------------------------
__global__ void __launch_bounds__(1024) recurse_kernel(const float* __restrict__ data)
{
    __shared__ float Vs[2][8 * NVEC];
    const int t  = threadIdx.x;
    const int d0 = blockIdx.x * 8;
    const int b  = blockIdx.y;

    const float4* p =
        reinterpret_cast<const float4*>(data + ((size_t)(b * NVEC) + t) * NDIM + d0);
    float4 A  = __ldg(p);
    float4 Bv = __ldg(p + 1);
    float acc[8] = {A.x, A.y, A.z, A.w, Bv.x, Bv.y, Bv.z, Bv.w};
#pragma unroll
    for (int d = 0; d < 8; d++) Vs[0][d * NVEC + t] = acc[d];

    const int OFF[NOFF] = {0, 1, 2, 4, 8, 16, 32, 64, 128, 256, 512};
    float wv[NOFF];
    {
        const float* w = g_w + (size_t)((9 * NB + b) * NOFF) * NVEC;
#pragma unroll
        for (int o = 0; o < NOFF; o++) wv[o] = __ldg(&w[o * NVEC + t]);
    }
    __syncthreads();

    int cur = 0;
#pragma unroll
    for (int i = NW - 1; i >= 0; i--) {
        float wn[NOFF];
        if (i > 0) {
            const float* w = g_w + (size_t)(((i - 1) * NB + b) * NOFF) * NVEC;
#pragma unroll
            for (int o = 0; o < NOFF; o++) wn[o] = __ldg(&w[o * NVEC + t]);
        }

        float na[8];
#pragma unroll
        for (int d = 0; d < 8; d++)
            na[d] = acc[d] + wv[0] * acc[d];
#pragma unroll
        for (int o = 1; o < NOFF; o++) {
            int m = (t + OFF[o]) & (NVEC - 1);
#pragma unroll
            for (int d = 0; d < 8; d++) na[d] += wv[o] * Vs[cur][d * NVEC + m];
        }
#pragma unroll
        for (int d = 0; d < 8; d++) {
            Vs[cur ^ 1][d * NVEC + t] = na[d];
            acc[d] = na[d];
        }
        __syncthreads();
        cur ^= 1;
#pragma unroll
        for (int o = 0; o < NOFF; o++) wv[o] = wn[o];
    }

    float* outp = g_V + ((size_t)(b * NVEC) + t) * NDIM + d0;
    *reinterpret_cast<float4*>(outp)     = make_float4(acc[0], acc[1], acc[2], acc[3]);
    *reinterpret_cast<float4*>(outp + 4) = make_float4(acc[4], acc[5], acc[6], acc[7]);
}

// ---------------------------------------------------------------------------
// Kernel 3: partial output GEMM + folded deterministic final reduction.
// ---------------------------------------------------------------------------
__global__ void __launch_bounds__(1024) partial_kernel(
    const float* __restrict__ finW, const float* __restrict__ finb,
    float* __restrict__ out)
{
    const int t  = threadIdx.x;
    const int ch = blockIdx.x;   // 0..7
    const int b  = blockIdx.y;
    const int f0 = ch * 8192 + t * 8;

    const float* Vb = g_V + ((size_t)b << 16);
    float4 v0 = *reinterpret_cast<const float4*>(Vb + f0);
    float4 v1 = *reinterpret_cast<const float4*>(Vb + f0 + 4);
    float vv[8] = {v0.x, v0.y, v0.z, v0.w, v1.x, v1.y, v1.z, v1.w};

    float acc[10];
#pragma unroll
    for (int c = 0; c < 10; c++) acc[c] = 0.f;

    const float4* Wp = reinterpret_cast<const float4*>(finW + (size_t)f0 * 10);
#pragma unroll
    for (int u = 0; u < 4; u++) {
        float4 w4[5];
#pragma unroll
        for (int j = 0; j < 5; j++) w4[j] = __ldg(Wp + u * 5 + j);
        const float* wf = reinterpret_cast<const float*>(w4);
        float va = vv[2 * u], vb = vv[2 * u + 1];
#pragma unroll
        for (int c = 0; c < 10; c++) acc[c] += va * wf[c];
#pragma unroll
        for (int c = 0; c < 10; c++) acc[c] += vb * wf[10 + c];
    }

#pragma unroll
    for (int c = 0; c < 10; c++) {
#pragma unroll
        for (int s = 16; s > 0; s >>= 1)
            acc[c] += __shfl_xor_sync(0xffffffffu, acc[c], s);
    }
    __shared__ float red[32 * 10];
    __shared__ int isLast;
    int lane = t & 31, wp = t >> 5;
    if (lane == 0) {
#pragma unroll
        for (int c = 0; c < 10; c++) red[wp * 10 + c] = acc[c];
    }
    __syncthreads();
    if (t < 10) {
        float s = 0.f;
        for (int w_ = 0; w_ < 32; w_++) s += red[w_ * 10 + t];
        g_part[(b * 8 + ch) * 10 + t] = s;
    }
    __threadfence();
    if (t == 0) {
        int old = atomicAdd(&g_cnt, 1);
        isLast = (old == NB * 8 - 1);
    }
    __syncthreads();
    if (isLast) {
        __threadfence();
        if (t == 0) g_cnt = 0;
        if (t < NB * 10) {
            int bb = t / 10, c = t - bb * 10;
            float s = finb[c];
#pragma unroll
            for (int cc = 0; cc < 8; cc++) s += g_part[(bb * 8 + cc) * 10 + c];
            out[t] = s;
        }
    }
}

// ---------------------------------------------------------------------------
extern "C" void kernel_launch(void* const* d_in, const int* in_sizes, int n_in,
                              void* d_out, int out_size)
{
    const float* data = (const float*)d_in[0];
    const float* fW1  = (const float*)d_in[1];
    const float* fb1  = (const float*)d_in[2];
    const float* fW2  = (const float*)d_in[3];
    const float* fb2  = (const float*)d_in[4];
    const float* finW = (const float*)d_in[5];
    const float* finb = (const float*)d_in[6];
    float* out = (float*)d_out;

    cudaFuncSetAttribute(precompute_kernel,
                         cudaFuncAttributeMaxDynamicSharedMemorySize, PRE_SMEM);

    precompute_kernel<<<dim3(4, 8, 10), 256, PRE_SMEM>>>(data, fW1, fb1, fW2, fb2);
    recurse_kernel<<<dim3(8, 16), 1024>>>(data);
    partial_kernel<<<dim3(8, 16), 1024>>>(finW, finb, out);
}

// round 4
// speedup vs baseline: 1.1986x; 1.1986x over previous
#include <cuda_runtime.h>
#include <cstdint>
#include <cstddef>

#define NVEC 1024
#define NDIM 64
#define NHID 32
#define NW   10
#define NB   16
#define NOFF 11

// Scratch (no allocations allowed): device globals.
__device__ float g_w[NW * NB * NOFF * NVEC];   // sparse W values [i][b][o][n]
__device__ float g_H[NW * NB * NVEC * NHID];   // gelu hidden activations (21MB)
__device__ float g_fW2T[NW * NVEC * NHID];     // fW2 transposed [i][n][h]
__device__ float g_V[NB * NVEC * NDIM];        // final V
__device__ float g_part[NB * 8 * 10];          // partial sums for output GEMM
__device__ int   g_cnt;                        // block completion counter

// ---------- f32x2 packed helpers (sm_103a FFMA2) ----------
__device__ __forceinline__ unsigned long long pack2(float x, float y) {
    unsigned long long r;
    asm("mov.b64 %0, {%1, %2};" : "=l"(r) : "f"(x), "f"(y));
    return r;
}
__device__ __forceinline__ void fma2(unsigned long long& d, unsigned long long a, unsigned long long b) {
    asm("fma.rn.f32x2 %0, %1, %2, %0;" : "+l"(d) : "l"(a), "l"(b));
}
__device__ __forceinline__ float2 unpack2(unsigned long long v) {
    float lo, hi;
    asm("mov.b64 {%0, %1}, %2;" : "=f"(lo), "=f"(hi) : "l"(v));
    return make_float2(lo, hi);
}
__device__ __forceinline__ float gelu_exact(float x) {
    return 0.5f * x * (1.0f + erff(x * 0.70710678f));
}

// ---------------------------------------------------------------------------
// Kernel A: H = gelu(X @ fW1 + fb1) for all (i,b), register-tiled 4n x 8h.
// Small smem (75KB) -> 3 CTAs / 24 warps per SM. grid (4, 16, 11); z==10
// blocks instead transpose fW2 -> g_fW2T.
// ---------------------------------------------------------------------------
#define XS 65
#define H_SMEM ((NDIM * NHID + NHID + 256 * XS) * 4)   // 74880 B

__global__ void __launch_bounds__(256, 3) h_kernel(
    const float* __restrict__ data, const float* __restrict__ fW1,
    const float* __restrict__ fb1,  const float* __restrict__ fW2)
{
    extern __shared__ float sm[];
    const int t = threadIdx.x;

    // ---------------- transpose branch ----------------
    if (blockIdx.z == NW) {
        int idx = blockIdx.y * 4 + blockIdx.x;     // 0..63
        if (idx >= 2 * NW) return;
        const int i  = idx >> 1;
        const int c0 = (idx & 1) * 512;
        float* tile = sm;                          // [32][33]
        for (int s = 0; s < 16; s++) {
#pragma unroll
            for (int it = 0; it < 4; it++) {
                int r = it * 8 + (t >> 5);
                int c = t & 31;
                tile[r * 33 + c] = fW2[((size_t)(i * NHID) + r) * NVEC + c0 + s * 32 + c];
            }
            __syncthreads();
            int cr = t >> 3, rg = t & 7;
            float4 v = make_float4(tile[(4 * rg + 0) * 33 + cr],
                                   tile[(4 * rg + 1) * 33 + cr],
                                   tile[(4 * rg + 2) * 33 + cr],
                                   tile[(4 * rg + 3) * 33 + cr]);
            *reinterpret_cast<float4*>(
                &g_fW2T[((size_t)(i * NVEC) + c0 + s * 32 + cr) * NHID + 4 * rg]) = v;
            __syncthreads();
        }
        return;
    }

    // ---------------- H branch ----------------
    float* sw1  = sm;                   // [64][32]
    float* sfb1 = sw1 + NDIM * NHID;    // [32]
    float* Xs   = sfb1 + NHID;          // [256][65]

    const int n0 = blockIdx.x * 256;
    const int b  = blockIdx.y;
    const int i  = blockIdx.z;

    for (int idx = t; idx < NDIM * NHID; idx += 256)
        sw1[idx] = fW1[i * NDIM * NHID + idx];
    if (t < NHID) sfb1[t] = fb1[i * NHID + t];

    const float4* src =
        reinterpret_cast<const float4*>(data + ((size_t)b * NVEC + n0) * NDIM);
#pragma unroll
    for (int j = 0; j < 16; j++) {
        int p  = t + 256 * j;
        int n  = p >> 4;
        int kq = p & 15;
        float4 v = __ldg(src + p);
        float* dst = Xs + n * XS + kq * 4;
        dst[0] = v.x; dst[1] = v.y; dst[2] = v.z; dst[3] = v.w;
    }
    __syncthreads();

    const int ht8 = (t & 3) * 8;
    const int nb  = (t >> 2) * 4;

    unsigned long long acc[4][4];
    {
        const unsigned long long* bp =
            reinterpret_cast<const unsigned long long*>(&sfb1[ht8]);
        unsigned long long b0 = bp[0], b1 = bp[1], b2 = bp[2], b3 = bp[3];
#pragma unroll
        for (int j = 0; j < 4; j++) {
            acc[j][0] = b0; acc[j][1] = b1; acc[j][2] = b2; acc[j][3] = b3;
        }
    }
#pragma unroll 8
    for (int k = 0; k < NDIM; k++) {
        const unsigned long long* wp =
            reinterpret_cast<const unsigned long long*>(&sw1[k * NHID + ht8]);
        unsigned long long w0 = wp[0], w1 = wp[1], w2 = wp[2], w3 = wp[3];
#pragma unroll
        for (int j = 0; j < 4; j++) {
            float xv = Xs[(nb + j) * XS + k];
            unsigned long long xx = pack2(xv, xv);
            fma2(acc[j][0], xx, w0);
            fma2(acc[j][1], xx, w1);
            fma2(acc[j][2], xx, w2);
            fma2(acc[j][3], xx, w3);
        }
    }

    // gelu + store H rows (2x STG.128 per row).
    float* Hbase = g_H + ((size_t)(i * NB + b) * NVEC) * NHID;
#pragma unroll
    for (int j = 0; j < 4; j++) {
        float2 v0 = unpack2(acc[j][0]);
        float2 v1 = unpack2(acc[j][1]);
        float2 v2 = unpack2(acc[j][2]);
        float2 v3 = unpack2(acc[j][3]);
        float4 a = make_float4(gelu_exact(v0.x), gelu_exact(v0.y),
                               gelu_exact(v1.x), gelu_exact(v1.y));
        float4 c = make_float4(gelu_exact(v2.x), gelu_exact(v2.y),
                               gelu_exact(v3.x), gelu_exact(v3.y));
        float* dst = Hbase + (size_t)(n0 + nb + j) * NHID + ht8;
        reinterpret_cast<float4*>(dst)[0] = a;
        reinterpret_cast<float4*>(dst)[1] = c;
    }
}

// ---------------------------------------------------------------------------
// Kernel B: sparse W values.  Block = (b, i), 1024 threads (t = n).
// Full fW2T ring staged in smem [1024][36] (16B-aligned rows, LDS.128
// conflict-free). Thread reads its own H row once, then 11 offset dots.
// ---------------------------------------------------------------------------
#define FTS 36
#define W2_SMEM ((NVEC * FTS + NVEC) * 4)   // 151552 B

__global__ void __launch_bounds__(1024) w2_kernel(const float* __restrict__ fb2)
{
    extern __shared__ float sm[];
    float* sfT  = sm;              // [1024][36]
    float* sfb2 = sm + NVEC * FTS; // [1024]

    const int t = threadIdx.x;
    const int b = blockIdx.x;
    const int i = blockIdx.y;

    // Stage fW2T layer (coalesced LDG.128 -> conflict-free STS.128).
    const float4* src4 =
        reinterpret_cast<const float4*>(g_fW2T + (size_t)i * NVEC * NHID);
#pragma unroll
    for (int q = 0; q < 8; q++) {
        int p = t + 1024 * q;          // 8192 float4
        float4 v = src4[p];
        int n = p >> 3, c = (p & 7) << 2;
        *reinterpret_cast<float4*>(&sfT[n * FTS + c]) = v;
    }
    sfb2[t] = __ldg(&fb2[i * NVEC + t]);

    // Own H row -> registers (warp reads 4KB contiguous).
    float h[32];
    {
        const float4* hp = reinterpret_cast<const float4*>(
            g_H + ((size_t)(i * NB + b) * NVEC + t) * NHID);
#pragma unroll
        for (int q = 0; q < 8; q++) {
            float4 v = __ldg(hp + q);
            h[4 * q] = v.x; h[4 * q + 1] = v.y; h[4 * q + 2] = v.z; h[4 * q + 3] = v.w;
        }
    }
    __syncthreads();

    const int OFF[NOFF] = {0, 1, 2, 4, 8, 16, 32, 64, 128, 256, 512};
    float* out = g_w + (size_t)((i * NB + b) * NOFF) * NVEC + t;
#pragma unroll
    for (int o = 0; o < NOFF; o++) {
        int m = (t + OFF[o]) & (NVEC - 1);
        const float4* rp = reinterpret_cast<const float4*>(&sfT[m * FTS]);
        float s0 = 0.f, s1 = 0.f, s2 = 0.f, s3 = 0.f;
#pragma unroll
        for (int q = 0; q < 8; q++) {
            float4 w = rp[q];
            s0 = fmaf(h[4 * q],     w.x, s0);
            s1 = fmaf(h[4 * q + 1], w.y, s1);
            s2 = fmaf(h[4 * q + 2], w.z, s2);
            s3 = fmaf(h[4 * q + 3], w.w, s3);
        }
        out[(size_t)o * NVEC] = (s0 + s1) + (s2 + s3) + sfb2[m];
    }
}

// ---------------------------------------------------------------------------
// Kernel 2: the full 10-layer sparse recursion, V slice resident in smem.
// ---------------------------------------------------------------------------
__global__ void __launch_bounds__(1024) recurse_kernel(const float* __restrict__ data)
{
    __shared__ float Vs[2][8 * NVEC];
    const int t  = threadIdx.x;
    const int d0 = blockIdx.x * 8;
    const int b  = blockIdx.y;

    const float4* p =
        reinterpret_cast<const float4*>(data + ((size_t)(b * NVEC) + t) * NDIM + d0);
    float4 A  = __ldg(p);
    float4 Bv = __ldg(p + 1);
    float acc[8] = {A.x, A.y, A.z, A.w, Bv.x, Bv.y, Bv.z, Bv.w};
#pragma unroll
    for (int d = 0; d < 8; d++) Vs[0][d * NVEC + t] = acc[d];

    const int OFF[NOFF] = {0, 1, 2, 4, 8, 16, 32, 64, 128, 256, 512};
    float wv[NOFF];
    {
        const float* w = g_w + (size_t)((9 * NB + b) * NOFF) * NVEC;
#pragma unroll
        for (int o = 0; o < NOFF; o++) wv[o] = __ldg(&w[o * NVEC + t]);
    }
    __syncthreads();

    int cur = 0;
#pragma unroll
    for (int i = NW - 1; i >= 0; i--) {
        float wn[NOFF];
        if (i > 0) {
            const float* w = g_w + (size_t)(((i - 1) * NB + b) * NOFF) * NVEC;
#pragma unroll
            for (int o = 0; o < NOFF; o++) wn[o] = __ldg(&w[o * NVEC + t]);
        }

        float na[8];
#pragma unroll
        for (int d = 0; d < 8; d++)
            na[d] = acc[d] + wv[0] * acc[d];
#pragma unroll
        for (int o = 1; o < NOFF; o++) {
            int m = (t + OFF[o]) & (NVEC - 1);
#pragma unroll
            for (int d = 0; d < 8; d++) na[d] += wv[o] * Vs[cur][d * NVEC + m];
        }
#pragma unroll
        for (int d = 0; d < 8; d++) {
            Vs[cur ^ 1][d * NVEC + t] = na[d];
            acc[d] = na[d];
        }
        __syncthreads();
        cur ^= 1;
#pragma unroll
        for (int o = 0; o < NOFF; o++) wv[o] = wn[o];
    }

    float* outp = g_V + ((size_t)(b * NVEC) + t) * NDIM + d0;
    *reinterpret_cast<float4*>(outp)     = make_float4(acc[0], acc[1], acc[2], acc[3]);
    *reinterpret_cast<float4*>(outp + 4) = make_float4(acc[4], acc[5], acc[6], acc[7]);
}

// ---------------------------------------------------------------------------
// Kernel 3: partial output GEMM + folded deterministic final reduction.
// ---------------------------------------------------------------------------
__global__ void __launch_bounds__(1024) partial_kernel(
    const float* __restrict__ finW, const float* __restrict__ finb,
    float* __restrict__ out)
{
    const int t  = threadIdx.x;
    const int ch = blockIdx.x;
    const int b  = blockIdx.y;
    const int f0 = ch * 8192 + t * 8;

    const float* Vb = g_V + ((size_t)b << 16);
    float4 v0 = *reinterpret_cast<const float4*>(Vb + f0);
    float4 v1 = *reinterpret_cast<const float4*>(Vb + f0 + 4);
    float vv[8] = {v0.x, v0.y, v0.z, v0.w, v1.x, v1.y, v1.z, v1.w};

    float acc[10];
#pragma unroll
    for (int c = 0; c < 10; c++) acc[c] = 0.f;

    const float4* Wp = reinterpret_cast<const float4*>(finW + (size_t)f0 * 10);
#pragma unroll
    for (int u = 0; u < 4; u++) {
        float4 w4[5];
#pragma unroll
        for (int j = 0; j < 5; j++) w4[j] = __ldg(Wp + u * 5 + j);
        const float* wf = reinterpret_cast<const float*>(w4);
        float va = vv[2 * u], vb = vv[2 * u + 1];
#pragma unroll
        for (int c = 0; c < 10; c++) acc[c] += va * wf[c];
#pragma unroll
        for (int c = 0; c < 10; c++) acc[c] += vb * wf[10 + c];
    }

#pragma unroll
    for (int c = 0; c < 10; c++) {
#pragma unroll
        for (int s = 16; s > 0; s >>= 1)
            acc[c] += __shfl_xor_sync(0xffffffffu, acc[c], s);
    }
    __shared__ float red[32 * 10];
    __shared__ int isLast;
    int lane = t & 31, wp = t >> 5;
    if (lane == 0) {
#pragma unroll
        for (int c = 0; c < 10; c++) red[wp * 10 + c] = acc[c];
    }
    __syncthreads();
    if (t < 10) {
        float s = 0.f;
        for (int w_ = 0; w_ < 32; w_++) s += red[w_ * 10 + t];
        g_part[(b * 8 + ch) * 10 + t] = s;
    }
    __threadfence();
    if (t == 0) {
        int old = atomicAdd(&g_cnt, 1);
        isLast = (old == NB * 8 - 1);
    }
    __syncthreads();
    if (isLast) {
        __threadfence();
        if (t == 0) g_cnt = 0;
        if (t < NB * 10) {
            int bb = t / 10, c = t - bb * 10;
            float s = finb[c];
#pragma unroll
            for (int cc = 0; cc < 8; cc++) s += g_part[(bb * 8 + cc) * 10 + c];
            out[t] = s;
        }
    }
}

// ---------------------------------------------------------------------------
extern "C" void kernel_launch(void* const* d_in, const int* in_sizes, int n_in,
                              void* d_out, int out_size)
{
    const float* data = (const float*)d_in[0];
    const float* fW1  = (const float*)d_in[1];
    const float* fb1  = (const float*)d_in[2];
    const float* fW2  = (const float*)d_in[3];
    const float* fb2  = (const float*)d_in[4];
    const float* finW = (const float*)d_in[5];
    const float* finb = (const float*)d_in[6];
    float* out = (float*)d_out;

    cudaFuncSetAttribute(h_kernel,
                         cudaFuncAttributeMaxDynamicSharedMemorySize, H_SMEM);
    cudaFuncSetAttribute(w2_kernel,
                         cudaFuncAttributeMaxDynamicSharedMemorySize, W2_SMEM);

    h_kernel<<<dim3(4, 16, 11), 256, H_SMEM>>>(data, fW1, fb1, fW2);
    w2_kernel<<<dim3(16, 10), 1024, W2_SMEM>>>(fb2);
    recurse_kernel<<<dim3(8, 16), 1024>>>(data);
    partial_kernel<<<dim3(8, 16), 1024>>>(finW, finb, out);
}

// round 5
// speedup vs baseline: 1.2900x; 1.0762x over previous
#include <cuda_runtime.h>
#include <cstdint>
#include <cstddef>

#define NVEC 1024
#define NDIM 64
#define NHID 32
#define NW   10
#define NB   16
#define NOFF 11

// Scratch (no allocations allowed): device globals.
__device__ float g_w[NW * NB * NOFF * NVEC];   // sparse W values [i][b][o][n]
__device__ float g_H[NW * NB * NVEC * NHID];   // gelu hidden activations (21MB)
__device__ float g_fW2T[NW * NVEC * NHID];     // fW2 transposed [i][n][h]
__device__ float g_fWT[10 * 65536];            // final_W transposed [c][f] (2.6MB)
__device__ float g_V[NB * NVEC * NDIM];        // final V
__device__ float g_part[NB * 8 * 10];          // partial sums for output GEMM
__device__ int   g_cnt;                        // block completion counter

// ---------- f32x2 packed helpers (sm_103a FFMA2) ----------
__device__ __forceinline__ unsigned long long pack2(float x, float y) {
    unsigned long long r;
    asm("mov.b64 %0, {%1, %2};" : "=l"(r) : "f"(x), "f"(y));
    return r;
}
__device__ __forceinline__ void fma2(unsigned long long& d, unsigned long long a, unsigned long long b) {
    asm("fma.rn.f32x2 %0, %1, %2, %0;" : "+l"(d) : "l"(a), "l"(b));
}
__device__ __forceinline__ float2 unpack2(unsigned long long v) {
    float lo, hi;
    asm("mov.b64 {%0, %1}, %2;" : "=f"(lo), "=f"(hi) : "l"(v));
    return make_float2(lo, hi);
}
__device__ __forceinline__ float gelu_exact(float x) {
    return 0.5f * x * (1.0f + erff(x * 0.70710678f));
}

// ---------------------------------------------------------------------------
// Kernel A: H = gelu(X @ fW1 + fb1), register-tiled 4n x 8h (z = 0..9).
// z == 10: transpose fW2 -> g_fW2T.   z == 11: transpose finW -> g_fWT.
// ---------------------------------------------------------------------------
#define XS 65
#define H_SMEM ((NDIM * NHID + NHID + 256 * XS) * 4)   // 74880 B
#define TWS 1032                                       // finW transpose row pad

__global__ void __launch_bounds__(256, 3) h_kernel(
    const float* __restrict__ data, const float* __restrict__ fW1,
    const float* __restrict__ fb1,  const float* __restrict__ fW2,
    const float* __restrict__ finW)
{
    extern __shared__ float sm[];
    const int t = threadIdx.x;

    // ---------------- fW2 transpose branch ----------------
    if (blockIdx.z == NW) {
        int idx = blockIdx.y * 4 + blockIdx.x;     // 0..63
        if (idx >= 2 * NW) return;
        const int i  = idx >> 1;
        const int c0 = (idx & 1) * 512;
        float* tile = sm;                          // [32][33]
        for (int s = 0; s < 16; s++) {
#pragma unroll
            for (int it = 0; it < 4; it++) {
                int r = it * 8 + (t >> 5);
                int c = t & 31;
                tile[r * 33 + c] = fW2[((size_t)(i * NHID) + r) * NVEC + c0 + s * 32 + c];
            }
            __syncthreads();
            int cr = t >> 3, rg = t & 7;
            float4 v = make_float4(tile[(4 * rg + 0) * 33 + cr],
                                   tile[(4 * rg + 1) * 33 + cr],
                                   tile[(4 * rg + 2) * 33 + cr],
                                   tile[(4 * rg + 3) * 33 + cr]);
            *reinterpret_cast<float4*>(
                &g_fW2T[((size_t)(i * NVEC) + c0 + s * 32 + cr) * NHID + 4 * rg]) = v;
            __syncthreads();
        }
        return;
    }

    // ---------------- finW transpose branch ----------------
    if (blockIdx.z == NW + 1) {
        int idx = blockIdx.y * 4 + blockIdx.x;     // 0..63, tile = 1024 f-rows
        const int f0 = idx * 1024;
        float* sT = sm;                            // [10][TWS]
        const float4* src = reinterpret_cast<const float4*>(finW + (size_t)f0 * 10);
#pragma unroll
        for (int j = 0; j < 10; j++) {             // 2560 float4 in tile
            float4 v = __ldg(src + t + 256 * j);
            int e = 4 * (t + 256 * j);
            float vals[4] = {v.x, v.y, v.z, v.w};
#pragma unroll
            for (int u = 0; u < 4; u++) {
                int ee = e + u;
                int r = ee / 10, c = ee - 10 * r;
                sT[c * TWS + r] = vals[u];
            }
        }
        __syncthreads();
        float4* dst = reinterpret_cast<float4*>(g_fWT);
#pragma unroll
        for (int c = 0; c < 10; c++) {
            const float* s = &sT[c * TWS + 4 * t];
            dst[c * 16384 + (f0 >> 2) + t] = make_float4(s[0], s[1], s[2], s[3]);
        }
        return;
    }

    // ---------------- H branch ----------------
    float* sw1  = sm;                   // [64][32]
    float* sfb1 = sw1 + NDIM * NHID;    // [32]
    float* Xs   = sfb1 + NHID;          // [256][65]

    const int n0 = blockIdx.x * 256;
    const int b  = blockIdx.y;
    const int i  = blockIdx.z;

    for (int idx = t; idx < NDIM * NHID; idx += 256)
        sw1[idx] = fW1[i * NDIM * NHID + idx];
    if (t < NHID) sfb1[t] = fb1[i * NHID + t];

    const float4* src =
        reinterpret_cast<const float4*>(data + ((size_t)b * NVEC + n0) * NDIM);
#pragma unroll
    for (int j = 0; j < 16; j++) {
        int p  = t + 256 * j;
        int n  = p >> 4;
        int kq = p & 15;
        float4 v = __ldg(src + p);
        float* dst = Xs + n * XS + kq * 4;
        dst[0] = v.x; dst[1] = v.y; dst[2] = v.z; dst[3] = v.w;
    }
    __syncthreads();

    const int ht8 = (t & 3) * 8;
    const int nb  = (t >> 2) * 4;

    unsigned long long acc[4][4];
    {
        const unsigned long long* bp =
            reinterpret_cast<const unsigned long long*>(&sfb1[ht8]);
        unsigned long long b0 = bp[0], b1 = bp[1], b2 = bp[2], b3 = bp[3];
#pragma unroll
        for (int j = 0; j < 4; j++) {
            acc[j][0] = b0; acc[j][1] = b1; acc[j][2] = b2; acc[j][3] = b3;
        }
    }
#pragma unroll 8
    for (int k = 0; k < NDIM; k++) {
        const unsigned long long* wp =
            reinterpret_cast<const unsigned long long*>(&sw1[k * NHID + ht8]);
        unsigned long long w0 = wp[0], w1 = wp[1], w2 = wp[2], w3 = wp[3];
#pragma unroll
        for (int j = 0; j < 4; j++) {
            float xv = Xs[(nb + j) * XS + k];
            unsigned long long xx = pack2(xv, xv);
            fma2(acc[j][0], xx, w0);
            fma2(acc[j][1], xx, w1);
            fma2(acc[j][2], xx, w2);
            fma2(acc[j][3], xx, w3);
        }
    }

    float* Hbase = g_H + ((size_t)(i * NB + b) * NVEC) * NHID;
#pragma unroll
    for (int j = 0; j < 4; j++) {
        float2 v0 = unpack2(acc[j][0]);
        float2 v1 = unpack2(acc[j][1]);
        float2 v2 = unpack2(acc[j][2]);
        float2 v3 = unpack2(acc[j][3]);
        float4 a = make_float4(gelu_exact(v0.x), gelu_exact(v0.y),
                               gelu_exact(v1.x), gelu_exact(v1.y));
        float4 c = make_float4(gelu_exact(v2.x), gelu_exact(v2.y),
                               gelu_exact(v3.x), gelu_exact(v3.y));
        float* dst = Hbase + (size_t)(n0 + nb + j) * NHID + ht8;
        reinterpret_cast<float4*>(dst)[0] = a;
        reinterpret_cast<float4*>(dst)[1] = c;
    }
}

// ---------------------------------------------------------------------------
// Kernel B: sparse W values. Block = (b-pair, i), 1024 threads (t = n).
// fW2T ring staged once, then the TWO batches processed sequentially
// (register-light: h[] reused). grid (8, 10) = 80 blocks, single wave.
// ---------------------------------------------------------------------------
#define FTS 36
#define W2_SMEM ((NVEC * FTS + NVEC) * 4)   // 151552 B

__global__ void __launch_bounds__(1024) w2_kernel(const float* __restrict__ fb2)
{
    extern __shared__ float sm[];
    float* sfT  = sm;              // [1024][36]
    float* sfb2 = sm + NVEC * FTS; // [1024]

    const int t  = threadIdx.x;
    const int b0 = blockIdx.x * 2;
    const int i  = blockIdx.y;

    const float4* src4 =
        reinterpret_cast<const float4*>(g_fW2T + (size_t)i * NVEC * NHID);
#pragma unroll
    for (int q = 0; q < 8; q++) {
        int p = t + 1024 * q;
        float4 v = src4[p];
        int n = p >> 3, c = (p & 7) << 2;
        *reinterpret_cast<float4*>(&sfT[n * FTS + c]) = v;
    }
    sfb2[t] = __ldg(&fb2[i * NVEC + t]);
    __syncthreads();

    const int OFF[NOFF] = {0, 1, 2, 4, 8, 16, 32, 64, 128, 256, 512};

#pragma unroll 1
    for (int bb = 0; bb < 2; bb++) {
        const int b = b0 + bb;
        float h[32];
        const float4* hp = reinterpret_cast<const float4*>(
            g_H + ((size_t)(i * NB + b) * NVEC + t) * NHID);
#pragma unroll
        for (int q = 0; q < 8; q++) {
            float4 v = __ldg(hp + q);
            h[4 * q] = v.x; h[4 * q + 1] = v.y; h[4 * q + 2] = v.z; h[4 * q + 3] = v.w;
        }

        float* out = g_w + (size_t)((i * NB + b) * NOFF) * NVEC + t;
#pragma unroll
        for (int o = 0; o < NOFF; o++) {
            int m = (t + OFF[o]) & (NVEC - 1);
            const float4* rp = reinterpret_cast<const float4*>(&sfT[m * FTS]);
            float s0 = 0.f, s1 = 0.f, s2 = 0.f, s3 = 0.f;
#pragma unroll
            for (int q = 0; q < 8; q++) {
                float4 w = rp[q];
                s0 = fmaf(h[4 * q],     w.x, s0);
                s1 = fmaf(h[4 * q + 1], w.y, s1);
                s2 = fmaf(h[4 * q + 2], w.z, s2);
                s3 = fmaf(h[4 * q + 3], w.w, s3);
            }
            out[(size_t)o * NVEC] = (s0 + s1) + (s2 + s3) + sfb2[m];
        }
    }
}

// ---------------------------------------------------------------------------
// Kernel 2: the full 10-layer sparse recursion, V slice resident in smem.
// ---------------------------------------------------------------------------
__global__ void __launch_bounds__(1024) recurse_kernel(const float* __restrict__ data)
{
    __shared__ float Vs[2][8 * NVEC];
    const int t  = threadIdx.x;
    const int d0 = blockIdx.x * 8;
    const int b  = blockIdx.y;

    const float4* p =
        reinterpret_cast<const float4*>(data + ((size_t)(b * NVEC) + t) * NDIM + d0);
    float4 A  = __ldg(p);
    float4 Bv = __ldg(p + 1);
    float acc[8] = {A.x, A.y, A.z, A.w, Bv.x, Bv.y, Bv.z, Bv.w};
#pragma unroll
    for (int d = 0; d < 8; d++) Vs[0][d * NVEC + t] = acc[d];

    const int OFF[NOFF] = {0, 1, 2, 4, 8, 16, 32, 64, 128, 256, 512};
    float wv[NOFF];
    {
        const float* w = g_w + (size_t)((9 * NB + b) * NOFF) * NVEC;
#pragma unroll
        for (int o = 0; o < NOFF; o++) wv[o] = __ldg(&w[o * NVEC + t]);
    }
    __syncthreads();

    int cur = 0;
#pragma unroll
    for (int i = NW - 1; i >= 0; i--) {
        float wn[NOFF];
        if (i > 0) {
            const float* w = g_w + (size_t)(((i - 1) * NB + b) * NOFF) * NVEC;
#pragma unroll
            for (int o = 0; o < NOFF; o++) wn[o] = __ldg(&w[o * NVEC + t]);
        }

        float na[8];
#pragma unroll
        for (int d = 0; d < 8; d++)
            na[d] = acc[d] + wv[0] * acc[d];
#pragma unroll
        for (int o = 1; o < NOFF; o++) {
            int m = (t + OFF[o]) & (NVEC - 1);
#pragma unroll
            for (int d = 0; d < 8; d++) na[d] += wv[o] * Vs[cur][d * NVEC + m];
        }
#pragma unroll
        for (int d = 0; d < 8; d++) {
            Vs[cur ^ 1][d * NVEC + t] = na[d];
            acc[d] = na[d];
        }
        __syncthreads();
        cur ^= 1;
#pragma unroll
        for (int o = 0; o < NOFF; o++) wv[o] = wn[o];
    }

    float* outp = g_V + ((size_t)(b * NVEC) + t) * NDIM + d0;
    *reinterpret_cast<float4*>(outp)     = make_float4(acc[0], acc[1], acc[2], acc[3]);
    *reinterpret_cast<float4*>(outp + 4) = make_float4(acc[4], acc[5], acc[6], acc[7]);
}

// ---------------------------------------------------------------------------
// Kernel 3: partial output GEMM, fully coalesced via g_fWT, + folded
// deterministic final reduction (last block, fence + counter).
// ---------------------------------------------------------------------------
__global__ void __launch_bounds__(1024) partial_kernel(
    const float* __restrict__ finb, float* __restrict__ out)
{
    const int t  = threadIdx.x;
    const int ch = blockIdx.x;   // 0..7  (8192 f-values each)
    const int b  = blockIdx.y;

    const float4* Vb4 = reinterpret_cast<const float4*>(g_V + ((size_t)b << 16));
    const float4* W4  = reinterpret_cast<const float4*>(g_fWT);
    const int base = ch * 2048;   // float4 index within 16384-wide rows

    float4 v0 = Vb4[base + t];
    float4 v1 = Vb4[base + t + 1024];

    float acc[10];
#pragma unroll
    for (int c = 0; c < 10; c++) {
        float4 w0 = __ldg(&W4[c * 16384 + base + t]);
        float4 w1 = __ldg(&W4[c * 16384 + base + t + 1024]);
        float s = v0.x * w0.x + v0.y * w0.y + v0.z * w0.z + v0.w * w0.w;
        s += v1.x * w1.x + v1.y * w1.y + v1.z * w1.z + v1.w * w1.w;
        acc[c] = s;
    }

#pragma unroll
    for (int c = 0; c < 10; c++) {
#pragma unroll
        for (int s = 16; s > 0; s >>= 1)
            acc[c] += __shfl_xor_sync(0xffffffffu, acc[c], s);
    }
    __shared__ float red[32 * 10];
    __shared__ int isLast;
    int lane = t & 31, wp = t >> 5;
    if (lane == 0) {
#pragma unroll
        for (int c = 0; c < 10; c++) red[wp * 10 + c] = acc[c];
    }
    __syncthreads();
    if (t < 10) {
        float s = 0.f;
        for (int w_ = 0; w_ < 32; w_++) s += red[w_ * 10 + t];
        g_part[(b * 8 + ch) * 10 + t] = s;
    }
    __threadfence();
    if (t == 0) {
        int old = atomicAdd(&g_cnt, 1);
        isLast = (old == NB * 8 - 1);
    }
    __syncthreads();
    if (isLast) {
        __threadfence();
        if (t == 0) g_cnt = 0;
        if (t < NB * 10) {
            int bb = t / 10, c = t - bb * 10;
            float s = finb[c];
#pragma unroll
            for (int cc = 0; cc < 8; cc++) s += g_part[(bb * 8 + cc) * 10 + c];
            out[t] = s;
        }
    }
}

// ---------------------------------------------------------------------------
extern "C" void kernel_launch(void* const* d_in, const int* in_sizes, int n_in,
                              void* d_out, int out_size)
{
    const float* data = (const float*)d_in[0];
    const float* fW1  = (const float*)d_in[1];
    const float* fb1  = (const float*)d_in[2];
    const float* fW2  = (const float*)d_in[3];
    const float* fb2  = (const float*)d_in[4];
    const float* finW = (const float*)d_in[5];
    const float* finb = (const float*)d_in[6];
    float* out = (float*)d_out;

    cudaFuncSetAttribute(h_kernel,
                         cudaFuncAttributeMaxDynamicSharedMemorySize, H_SMEM);
    cudaFuncSetAttribute(w2_kernel,
                         cudaFuncAttributeMaxDynamicSharedMemorySize, W2_SMEM);

    h_kernel<<<dim3(4, 16, 12), 256, H_SMEM>>>(data, fW1, fb1, fW2, finW);
    w2_kernel<<<dim3(8, 10), 1024, W2_SMEM>>>(fb2);
    recurse_kernel<<<dim3(8, 16), 1024>>>(data);
    partial_kernel<<<dim3(8, 16), 1024>>>(finb, out);
}